// round 4
// baseline (speedup 1.0000x reference)
#include <cuda_runtime.h>
#include <cstdint>

#define HID    256
#define TDIM   1024
#define NSTEP  1023
#define IN_DIM 35

// output layout: coeff [256][1023][5] | mean [256][1023][5][32] | var [256][1023][5]
#define MEANBASE 1309440
#define VARBASE  43211520

// ---------------- device scratch (allocation-free) ----------------
__device__ float g_H[(size_t)NSTEP * 256 * 256];   // h history, [t][k=256][b=256]
__device__ float g_W1t[256 * 112];                 // k-major, M padded 100->112
__device__ float g_W2t[112 * 112];
__device__ float g_W3t[112 * 176];                 // M padded 170->176
__device__ float g_b1p[112];
__device__ float g_b2p[112];
__device__ float g_b3p[176];
__device__ unsigned g_bar[8];

// ---------------- prep: reset barriers, transpose/pad MDN weights ----------------
__global__ void prep_kernel(const float* __restrict__ W1, const float* __restrict__ b1,
                            const float* __restrict__ W2, const float* __restrict__ b2,
                            const float* __restrict__ W3, const float* __restrict__ b3)
{
    int id = blockIdx.x * blockDim.x + threadIdx.x;
    int stride = gridDim.x * blockDim.x;
    if (id < 8) g_bar[id] = 0u;
    for (int i = id; i < 256 * 112; i += stride) {
        int k = i / 112, m = i - k * 112;
        g_W1t[i] = (m < 100) ? W1[m * 256 + k] : 0.f;
    }
    for (int i = id; i < 112 * 112; i += stride) {
        int k = i / 112, m = i - k * 112;
        g_W2t[i] = (k < 100 && m < 100) ? W2[m * 100 + k] : 0.f;
    }
    for (int i = id; i < 112 * 176; i += stride) {
        int k = i / 176, m = i - k * 176;
        g_W3t[i] = (k < 100 && m < 170) ? W3[m * 100 + k] : 0.f;
    }
    for (int i = id; i < 112; i += stride) {
        g_b1p[i] = (i < 100) ? b1[i] : 0.f;
        g_b2p[i] = (i < 100) ? b2[i] : 0.f;
    }
    for (int i = id; i < 176; i += stride) g_b3p[i] = (i < 170) ? b3[i] : 0.f;
}

__device__ __forceinline__ float sigf(float v)     { return 1.f / (1.f + __expf(-v)); }
__device__ __forceinline__ float tanhfast(float v) { return 1.f - 2.f / (__expf(2.f * v) + 1.f); }

__device__ __forceinline__ float4 ldcg4(const float* p) {
    float4 v;
    asm volatile("ld.global.cg.v4.f32 {%0,%1,%2,%3},[%4];"
                 : "=f"(v.x), "=f"(v.y), "=f"(v.z), "=f"(v.w) : "l"(p));
    return v;
}

// ---------------- persistent LSTM ----------------
// grid 128: jg = blockIdx>>3 (16 hid-tiles of 16), bg = blockIdx&7 (8 batch-tiles of 32)
// 256 threads = 8 warps = 2 warps/SMSP.
#define LSTM_SMEM_BYTES ((256*64 + 36*64 + 64 + 256*32 + 36*32 + 64*36 + 16*32) * 4)

__global__ void __launch_bounds__(256, 1)
lstm_kernel(const float* __restrict__ x, const float* __restrict__ W_ih,
            const float* __restrict__ W_hh, const float* __restrict__ b_ih,
            const float* __restrict__ b_hh)
{
    extern __shared__ float sm[];
    float* Whh  = sm;               // [k=256][m=64] k-major
    float* Wih  = Whh + 256 * 64;   // [c=36][m=64]  (row 35 = zero pad)
    float* bias = Wih + 36 * 64;    // [64]
    float* hT   = bias + 64;        // [k=256][n=32]
    float* xT   = hT + 256 * 32;    // [c=36][n=32]
    float* Gs   = xT + 36 * 32;     // [m=64][ld=36]
    float* cS   = Gs + 64 * 36;     // [16][32] cell state

    const int tid = threadIdx.x;
    const int bg  = blockIdx.x & 7;
    const int jg  = blockIdx.x >> 3;

    // one-time weight staging (k-major transpose into smem)
    for (int i = tid; i < 64 * 64; i += 256) {
        int m  = i >> 6;
        int kc = (i & 63) << 2;
        int j  = ((m >> 4) << 8) + (jg << 4) + (m & 15);   // gate*256 + jg*16 + jh
        float4 w = *reinterpret_cast<const float4*>(&W_hh[j * 256 + kc]);
        Whh[(kc + 0) * 64 + m] = w.x;
        Whh[(kc + 1) * 64 + m] = w.y;
        Whh[(kc + 2) * 64 + m] = w.z;
        Whh[(kc + 3) * 64 + m] = w.w;
    }
    for (int i = tid; i < 36 * 64; i += 256) {
        int c = i >> 6, m = i & 63;
        int j = ((m >> 4) << 8) + (jg << 4) + (m & 15);
        Wih[c * 64 + m] = (c < 35) ? W_ih[j * 35 + c] : 0.f;
    }
    if (tid < 64) {
        int j = ((tid >> 4) << 8) + (jg << 4) + (tid & 15);
        bias[tid] = b_ih[j] + b_hh[j];
    }
    for (int i = tid; i < 512; i += 256) cS[i] = 0.f;
    if (tid < 32) xT[35 * 32 + tid] = 0.f;   // pad row, persists
    __syncthreads();

    const int tm  = tid & 15;          // GEMM: rows 4tm..4tm+3
    const int tb  = tid >> 4;          // GEMM: cols 2tb..2tb+1
    const int cjh = tid >> 4;          // combine: jh 0..15
    const int cn2 = (tid & 15) << 1;   // combine: col pair

    for (int t = 0; t < NSTEP; ++t) {
        // stage x [35][32]
        for (int i = tid; i < 32 * 35; i += 256) {
            int n = i / 35, c = i - n * 35;
            int b = (bg << 5) + n;
            xT[c * 32 + n] = x[((size_t)b * TDIM + t) * IN_DIM + c];
        }
        // stage h(t-1) [256][32] via L2 (bypass L1 — written by peer SMs)
        if (t > 0) {
            const float* hp = g_H + (size_t)(t - 1) * 65536 + (bg << 5);
            for (int i = tid; i < 2048; i += 256) {
                int k = i >> 3, nb = i & 7;
                float4 v = ldcg4(hp + (size_t)k * 256 + nb * 4);
                *reinterpret_cast<float4*>(&hT[k * 32 + nb * 4]) = v;
            }
        }
        __syncthreads();

        // GEMM 64x32, K = 36 + 256, register tile 4x2
        float acc[4][2];
#pragma unroll
        for (int i = 0; i < 4; ++i) { acc[i][0] = 0.f; acc[i][1] = 0.f; }

#pragma unroll 4
        for (int c = 0; c < 36; ++c) {
            float4 a  = *reinterpret_cast<const float4*>(&Wih[c * 64 + (tm << 2)]);
            float2 b2 = *reinterpret_cast<const float2*>(&xT[c * 32 + (tb << 1)]);
            float av[4] = {a.x, a.y, a.z, a.w};
#pragma unroll
            for (int i = 0; i < 4; ++i) {
                acc[i][0] = fmaf(av[i], b2.x, acc[i][0]);
                acc[i][1] = fmaf(av[i], b2.y, acc[i][1]);
            }
        }
        if (t > 0) {
#pragma unroll 8
            for (int k = 0; k < 256; ++k) {
                float4 a  = *reinterpret_cast<const float4*>(&Whh[k * 64 + (tm << 2)]);
                float2 b2 = *reinterpret_cast<const float2*>(&hT[k * 32 + (tb << 1)]);
                float av[4] = {a.x, a.y, a.z, a.w};
#pragma unroll
                for (int i = 0; i < 4; ++i) {
                    acc[i][0] = fmaf(av[i], b2.x, acc[i][0]);
                    acc[i][1] = fmaf(av[i], b2.y, acc[i][1]);
                }
            }
        }
#pragma unroll
        for (int i = 0; i < 4; ++i)
            *reinterpret_cast<float2*>(&Gs[((tm << 2) + i) * 36 + (tb << 1)]) =
                make_float2(acc[i][0], acc[i][1]);
        __syncthreads();

        // gate combine: 2 h-elements per thread; c stays in smem
        {
            float2 gi = *reinterpret_cast<const float2*>(&Gs[(cjh)      * 36 + cn2]);
            float2 gf = *reinterpret_cast<const float2*>(&Gs[(16 + cjh) * 36 + cn2]);
            float2 gg = *reinterpret_cast<const float2*>(&Gs[(32 + cjh) * 36 + cn2]);
            float2 go = *reinterpret_cast<const float2*>(&Gs[(48 + cjh) * 36 + cn2]);
            float bi = bias[cjh], bf = bias[16 + cjh], bgv = bias[32 + cjh], bo = bias[48 + cjh];
            float2 co = *reinterpret_cast<const float2*>(&cS[cjh * 32 + cn2]);
            float2 cn, hn;
#define COMB(L) { float iv = sigf(gi.L + bi); float fv = sigf(gf.L + bf);          \
                  float gv = tanhfast(gg.L + bgv); float ov = sigf(go.L + bo);     \
                  float cv = fv * co.L + iv * gv; cn.L = cv; hn.L = ov * tanhfast(cv); }
            COMB(x) COMB(y)
#undef COMB
            *reinterpret_cast<float2*>(&cS[cjh * 32 + cn2]) = cn;
            float* hout = g_H + (size_t)t * 65536 + (size_t)(((jg << 4) + cjh) << 8)
                          + (bg << 5) + cn2;
            *reinterpret_cast<float2*>(hout) = hn;
        }
        __threadfence();   // release: h visible before the flag
        __syncthreads();

        // barrier among the 16 jg-blocks sharing this bg
        if (tid == 0) {
            atomicAdd(&g_bar[bg], 1u);
            unsigned target = (unsigned)(t + 1) << 4;
            unsigned v;
            for (;;) {
                asm volatile("ld.acquire.gpu.global.u32 %0,[%1];"
                             : "=r"(v) : "l"(&g_bar[bg]));
                if (v >= target) break;
                __nanosleep(32);
            }
        }
        __syncthreads();
    }
}

// ---------------- MDN head ----------------
__device__ __forceinline__ void mdn_gemm(
    const float* __restrict__ At, int ldA, int mTiles, int K,
    const float* __restrict__ Bs, int ldb, float* __restrict__ Cs,
    const float* __restrict__ biasv, bool relu)
{
    for (int tile = threadIdx.x; tile < mTiles * 8; tile += blockDim.x) {
        int tm = tile % mTiles, tb = tile / mTiles;
        int m = tm << 2;
        const float* Ap = At + m;
        const float* Bp = Bs + (tb << 2);
        float acc[4][4];
#pragma unroll
        for (int i = 0; i < 4; ++i)
#pragma unroll
            for (int j = 0; j < 4; ++j) acc[i][j] = 0.f;
#pragma unroll 4
        for (int k = 0; k < K; ++k) {
            float4 a  = *reinterpret_cast<const float4*>(Ap + k * ldA);
            float4 b4 = *reinterpret_cast<const float4*>(Bp + k * ldb);
            float av[4] = {a.x, a.y, a.z, a.w};
            float bv[4] = {b4.x, b4.y, b4.z, b4.w};
#pragma unroll
            for (int i = 0; i < 4; ++i)
#pragma unroll
                for (int j = 0; j < 4; ++j) acc[i][j] = fmaf(av[i], bv[j], acc[i][j]);
        }
#pragma unroll
        for (int i = 0; i < 4; ++i) {
            float bv = biasv[m + i];
            float4 r = make_float4(acc[i][0] + bv, acc[i][1] + bv,
                                   acc[i][2] + bv, acc[i][3] + bv);
            if (relu) { r.x = fmaxf(r.x, 0.f); r.y = fmaxf(r.y, 0.f);
                        r.z = fmaxf(r.z, 0.f); r.w = fmaxf(r.w, 0.f); }
            *reinterpret_cast<float4*>(&Cs[(m + i) * 36 + (tb << 2)]) = r;
        }
    }
}

// smem: hT [256][32] (reused as h2 [112][36]) + h1 [112][36] + o3 [176][36]
#define MDN_SMEM_BYTES ((256*32 + 112*36 + 176*36) * 4)

__global__ void __launch_bounds__(256, 2)
mdn_kernel(float* __restrict__ out)
{
    extern __shared__ float sm[];
    float* hT = sm;                 // [256][32], reused as h2 [112][36]
    float* h1 = hT + 256 * 32;      // [112][36]
    float* o3 = h1 + 112 * 36;      // [176][36]

    const int tid = threadIdx.x;
    const int t   = blockIdx.x >> 3;
    const int bg  = blockIdx.x & 7;

    // stage h [256][32] (already k-major in g_H)
    const float* hp = g_H + (size_t)t * 65536 + (bg << 5);
    for (int i = tid; i < 2048; i += 256) {
        int k = i >> 3, nb = i & 7;
        float4 v = *reinterpret_cast<const float4*>(hp + (size_t)k * 256 + nb * 4);
        *reinterpret_cast<float4*>(&hT[k * 32 + nb * 4]) = v;
    }
    __syncthreads();

    mdn_gemm(g_W1t, 112, 28, 256, hT, 32, h1, g_b1p, true);
    __syncthreads();
    mdn_gemm(g_W2t, 112, 28, 112, h1, 36, hT, g_b2p, true);   // h2 -> hT (reuse)
    __syncthreads();
    mdn_gemm(g_W3t, 176, 44, 112, hT, 36, o3, g_b3p, false);
    __syncthreads();

    // epilogue: softmax(first 5), exp(next 5), copy means (160)
    if (tid < 32) {
        int n = tid;
        size_t r = (size_t)((bg << 5) + n) * NSTEP + t;
        float l[5];
        float mx = -1e30f;
#pragma unroll
        for (int k = 0; k < 5; ++k) { l[k] = o3[k * 36 + n]; mx = fmaxf(mx, l[k]); }
        float s = 0.f;
#pragma unroll
        for (int k = 0; k < 5; ++k) { l[k] = __expf(l[k] - mx); s += l[k]; }
        float inv = 1.f / s;
#pragma unroll
        for (int k = 0; k < 5; ++k) out[r * 5 + k] = l[k] * inv;
#pragma unroll
        for (int k = 0; k < 5; ++k)
            out[VARBASE + r * 5 + k] = __expf(o3[(5 + k) * 36 + n]);
    }
    for (int i = tid; i < 5120; i += 256) {
        int n = i / 160, j = i - n * 160;
        size_t r = (size_t)((bg << 5) + n) * NSTEP + t;
        out[MEANBASE + r * 160 + j] = o3[(10 + j) * 36 + n];
    }
}

extern "C" void kernel_launch(void* const* d_in, const int* in_sizes, int n_in,
                              void* d_out, int out_size)
{
    const float* x    = (const float*)d_in[0];
    const float* W_ih = (const float*)d_in[1];
    const float* W_hh = (const float*)d_in[2];
    const float* b_ih = (const float*)d_in[3];
    const float* b_hh = (const float*)d_in[4];
    const float* W1   = (const float*)d_in[5];
    const float* b1   = (const float*)d_in[6];
    const float* W2   = (const float*)d_in[7];
    const float* b2   = (const float*)d_in[8];
    const float* W3   = (const float*)d_in[9];
    const float* b3   = (const float*)d_in[10];
    float* out = (float*)d_out;

    cudaFuncSetAttribute(lstm_kernel, cudaFuncAttributeMaxDynamicSharedMemorySize, LSTM_SMEM_BYTES);
    cudaFuncSetAttribute(mdn_kernel,  cudaFuncAttributeMaxDynamicSharedMemorySize, MDN_SMEM_BYTES);

    prep_kernel<<<128, 256>>>(W1, b1, W2, b2, W3, b3);
    lstm_kernel<<<128, 256, LSTM_SMEM_BYTES>>>(x, W_ih, W_hh, b_ih, b_hh);
    mdn_kernel<<<NSTEP * 8, 256, MDN_SMEM_BYTES>>>(out);
}

// round 5
// speedup vs baseline: 1.0869x; 1.0869x over previous
#include <cuda_runtime.h>
#include <cstdint>

#define HID    256
#define TDIM   1024
#define NSTEP  1023
#define IN_DIM 35

// output layout: coeff [256][1023][5] | mean [256][1023][5][32] | var [256][1023][5]
#define MEANBASE 1309440
#define VARBASE  43211520

// ---------------- device scratch (allocation-free) ----------------
__device__ float g_H[(size_t)NSTEP * 256 * 256];   // h history, [t][k=256][b=256]
__device__ float g_W1t[256 * 112];                 // k-major, M padded 100->112
__device__ float g_W2t[112 * 112];
__device__ float g_W3t[112 * 176];                 // M padded 170->176
__device__ float g_b1p[112];
__device__ float g_b2p[112];
__device__ float g_b3p[176];
__device__ unsigned g_bar[8];

// ---------------- prep: reset barriers, transpose/pad MDN weights ----------------
__global__ void prep_kernel(const float* __restrict__ W1, const float* __restrict__ b1,
                            const float* __restrict__ W2, const float* __restrict__ b2,
                            const float* __restrict__ W3, const float* __restrict__ b3)
{
    int id = blockIdx.x * blockDim.x + threadIdx.x;
    int stride = gridDim.x * blockDim.x;
    if (id < 8) g_bar[id] = 0u;
    for (int i = id; i < 256 * 112; i += stride) {
        int k = i / 112, m = i - k * 112;
        g_W1t[i] = (m < 100) ? W1[m * 256 + k] : 0.f;
    }
    for (int i = id; i < 112 * 112; i += stride) {
        int k = i / 112, m = i - k * 112;
        g_W2t[i] = (k < 100 && m < 100) ? W2[m * 100 + k] : 0.f;
    }
    for (int i = id; i < 112 * 176; i += stride) {
        int k = i / 176, m = i - k * 176;
        g_W3t[i] = (k < 100 && m < 170) ? W3[m * 100 + k] : 0.f;
    }
    for (int i = id; i < 112; i += stride) {
        g_b1p[i] = (i < 100) ? b1[i] : 0.f;
        g_b2p[i] = (i < 100) ? b2[i] : 0.f;
    }
    for (int i = id; i < 176; i += stride) g_b3p[i] = (i < 170) ? b3[i] : 0.f;
}

__device__ __forceinline__ float sigf(float v)     { return 1.f / (1.f + __expf(-v)); }
__device__ __forceinline__ float tanhfast(float v) { return 1.f - 2.f / (__expf(2.f * v) + 1.f); }

__device__ __forceinline__ float4 ldcg4(const float* p) {
    float4 v;
    asm volatile("ld.global.cg.v4.f32 {%0,%1,%2,%3},[%4];"
                 : "=f"(v.x), "=f"(v.y), "=f"(v.z), "=f"(v.w) : "l"(p));
    return v;
}

// ---------------- persistent LSTM ----------------
// grid 128: jg = blockIdx>>3 (16 hid-tiles of 16), bg = blockIdx&7 (8 batch-tiles of 32)
// 256 threads = 2 warps/SMSP. Warp-group 0: x-part + h-k[0,110); group 1: h-k[110,256).
#define KSPLIT 110
#define LSTM_SMEM_BYTES ((256*64 + 36*64 + 64 + 256*32 + 36*32 + 2*64*36 + 16*32) * 4)

__global__ void __launch_bounds__(256, 1)
lstm_kernel(const float* __restrict__ x, const float* __restrict__ W_ih,
            const float* __restrict__ W_hh, const float* __restrict__ b_ih,
            const float* __restrict__ b_hh)
{
    extern __shared__ float sm[];
    float* Whh  = sm;               // [k=256][m=64] k-major
    float* Wih  = Whh + 256 * 64;   // [c=36][m=64]  (row 35 = zero pad)
    float* bias = Wih + 36 * 64;    // [64]
    float* hT   = bias + 64;        // [k=256][n=32]
    float* xT   = hT + 256 * 32;    // [c=36][n=32]
    float* Gs0  = xT + 36 * 32;     // [m=64][ld=36] partial sums, warp-group 0
    float* Gs1  = Gs0 + 64 * 36;    // [m=64][ld=36] partial sums, warp-group 1
    float* cS   = Gs1 + 64 * 36;    // [16][32] cell state

    const int tid = threadIdx.x;
    const int bg  = blockIdx.x & 7;
    const int jg  = blockIdx.x >> 3;

    // one-time weight staging (k-major transpose into smem)
    for (int i = tid; i < 64 * 64; i += 256) {
        int m  = i >> 6;
        int kc = (i & 63) << 2;
        int j  = ((m >> 4) << 8) + (jg << 4) + (m & 15);   // gate*256 + jg*16 + jh
        float4 w = *reinterpret_cast<const float4*>(&W_hh[j * 256 + kc]);
        Whh[(kc + 0) * 64 + m] = w.x;
        Whh[(kc + 1) * 64 + m] = w.y;
        Whh[(kc + 2) * 64 + m] = w.z;
        Whh[(kc + 3) * 64 + m] = w.w;
    }
    for (int i = tid; i < 36 * 64; i += 256) {
        int c = i >> 6, m = i & 63;
        int j = ((m >> 4) << 8) + (jg << 4) + (m & 15);
        Wih[c * 64 + m] = (c < 35) ? W_ih[j * 35 + c] : 0.f;
    }
    if (tid < 64) {
        int j = ((tid >> 4) << 8) + (jg << 4) + (tid & 15);
        bias[tid] = b_ih[j] + b_hh[j];
    }
    for (int i = tid; i < 512; i += 256) cS[i] = 0.f;
    if (tid < 32) xT[35 * 32 + tid] = 0.f;   // pad row, persists
    __syncthreads();

    const int wg   = tid >> 7;        // warp-group (K split)
    const int wtid = tid & 127;
    const int tm   = wtid & 15;       // GEMM: rows 4tm..4tm+3
    const int tb   = wtid >> 4;       // GEMM: cols 4tb..4tb+3
    float* Gs      = wg ? Gs1 : Gs0;

    const int cjh = tid >> 4;         // combine: jh 0..15
    const int cn2 = (tid & 15) << 1;  // combine: col pair

    for (int t = 0; t < NSTEP; ++t) {
        // stage x [35][32]
        for (int i = tid; i < 32 * 35; i += 256) {
            int n = i / 35, c = i - n * 35;
            int b = (bg << 5) + n;
            xT[c * 32 + n] = x[((size_t)b * TDIM + t) * IN_DIM + c];
        }
        // stage h(t-1) [256][32] via L2 (written by peer SMs)
        if (t > 0) {
            const float* hp = g_H + (size_t)(t - 1) * 65536 + (bg << 5);
            for (int i = tid; i < 2048; i += 256) {
                int k = i >> 3, nb = i & 7;
                float4 v = ldcg4(hp + (size_t)k * 256 + nb * 4);
                *reinterpret_cast<float4*>(&hT[k * 32 + nb * 4]) = v;
            }
        }
        __syncthreads();

        // GEMM 64x32, K = 36 + 256, split across two warp-groups, 4x4 tiles
        float acc[4][4];
#pragma unroll
        for (int i = 0; i < 4; ++i)
#pragma unroll
            for (int j = 0; j < 4; ++j) acc[i][j] = 0.f;

        if (wg == 0) {
#pragma unroll 4
            for (int c = 0; c < 36; ++c) {
                float4 a  = *reinterpret_cast<const float4*>(&Wih[c * 64 + (tm << 2)]);
                float4 b4 = *reinterpret_cast<const float4*>(&xT[c * 32 + (tb << 2)]);
                float av[4] = {a.x, a.y, a.z, a.w};
                float bv[4] = {b4.x, b4.y, b4.z, b4.w};
#pragma unroll
                for (int i = 0; i < 4; ++i)
#pragma unroll
                    for (int j = 0; j < 4; ++j) acc[i][j] = fmaf(av[i], bv[j], acc[i][j]);
            }
            if (t > 0) {
#pragma unroll 5
                for (int k = 0; k < KSPLIT; ++k) {
                    float4 a  = *reinterpret_cast<const float4*>(&Whh[k * 64 + (tm << 2)]);
                    float4 b4 = *reinterpret_cast<const float4*>(&hT[k * 32 + (tb << 2)]);
                    float av[4] = {a.x, a.y, a.z, a.w};
                    float bv[4] = {b4.x, b4.y, b4.z, b4.w};
#pragma unroll
                    for (int i = 0; i < 4; ++i)
#pragma unroll
                        for (int j = 0; j < 4; ++j) acc[i][j] = fmaf(av[i], bv[j], acc[i][j]);
                }
            }
        } else if (t > 0) {
#pragma unroll 2
            for (int k = KSPLIT; k < 256; ++k) {
                float4 a  = *reinterpret_cast<const float4*>(&Whh[k * 64 + (tm << 2)]);
                float4 b4 = *reinterpret_cast<const float4*>(&hT[k * 32 + (tb << 2)]);
                float av[4] = {a.x, a.y, a.z, a.w};
                float bv[4] = {b4.x, b4.y, b4.z, b4.w};
#pragma unroll
                for (int i = 0; i < 4; ++i)
#pragma unroll
                    for (int j = 0; j < 4; ++j) acc[i][j] = fmaf(av[i], bv[j], acc[i][j]);
            }
        }
#pragma unroll
        for (int i = 0; i < 4; ++i)
            *reinterpret_cast<float4*>(&Gs[((tm << 2) + i) * 36 + (tb << 2)]) =
                make_float4(acc[i][0], acc[i][1], acc[i][2], acc[i][3]);
        __syncthreads();

        // gate combine: sum both K-partials; c stays in smem; h -> global
        {
            float2 gi0 = *reinterpret_cast<const float2*>(&Gs0[(cjh)      * 36 + cn2]);
            float2 gf0 = *reinterpret_cast<const float2*>(&Gs0[(16 + cjh) * 36 + cn2]);
            float2 gg0 = *reinterpret_cast<const float2*>(&Gs0[(32 + cjh) * 36 + cn2]);
            float2 go0 = *reinterpret_cast<const float2*>(&Gs0[(48 + cjh) * 36 + cn2]);
            float2 gi1 = *reinterpret_cast<const float2*>(&Gs1[(cjh)      * 36 + cn2]);
            float2 gf1 = *reinterpret_cast<const float2*>(&Gs1[(16 + cjh) * 36 + cn2]);
            float2 gg1 = *reinterpret_cast<const float2*>(&Gs1[(32 + cjh) * 36 + cn2]);
            float2 go1 = *reinterpret_cast<const float2*>(&Gs1[(48 + cjh) * 36 + cn2]);
            float bi = bias[cjh], bf = bias[16 + cjh], bgv = bias[32 + cjh], bo = bias[48 + cjh];
            float2 co = *reinterpret_cast<const float2*>(&cS[cjh * 32 + cn2]);
            float2 cn, hn;
#define COMB(L) { float iv = sigf(gi0.L + gi1.L + bi);                              \
                  float fv = sigf(gf0.L + gf1.L + bf);                              \
                  float gv = tanhfast(gg0.L + gg1.L + bgv);                         \
                  float ov = sigf(go0.L + go1.L + bo);                              \
                  float cv = fv * co.L + iv * gv; cn.L = cv; hn.L = ov * tanhfast(cv); }
            COMB(x) COMB(y)
#undef COMB
            *reinterpret_cast<float2*>(&cS[cjh * 32 + cn2]) = cn;
            float* hout = g_H + (size_t)t * 65536 + (size_t)(((jg << 4) + cjh) << 8)
                          + (bg << 5) + cn2;
            *reinterpret_cast<float2*>(hout) = hn;
        }
        __syncthreads();

        // inter-block barrier (16 jg-blocks sharing this bg), CG-style release
        if (tid == 0) {
            __threadfence();
            asm volatile("red.release.gpu.global.add.u32 [%0],%1;"
                         :: "l"(&g_bar[bg]), "r"(1u) : "memory");
            unsigned target = (unsigned)(t + 1) << 4;
            unsigned v;
            do {
                asm volatile("ld.acquire.gpu.global.u32 %0,[%1];"
                             : "=r"(v) : "l"(&g_bar[bg]));
            } while (v < target);
        }
        __syncthreads();
    }
}

// ---------------- MDN head ----------------
__device__ __forceinline__ void mdn_gemm(
    const float* __restrict__ At, int ldA, int mTiles, int K,
    const float* __restrict__ Bs, int ldb, float* __restrict__ Cs,
    const float* __restrict__ biasv, bool relu)
{
    for (int tile = threadIdx.x; tile < mTiles * 8; tile += blockDim.x) {
        int tm = tile % mTiles, tb = tile / mTiles;
        int m = tm << 2;
        const float* Ap = At + m;
        const float* Bp = Bs + (tb << 2);
        float acc[4][4];
#pragma unroll
        for (int i = 0; i < 4; ++i)
#pragma unroll
            for (int j = 0; j < 4; ++j) acc[i][j] = 0.f;
#pragma unroll 4
        for (int k = 0; k < K; ++k) {
            float4 a  = *reinterpret_cast<const float4*>(Ap + k * ldA);
            float4 b4 = *reinterpret_cast<const float4*>(Bp + k * ldb);
            float av[4] = {a.x, a.y, a.z, a.w};
            float bv[4] = {b4.x, b4.y, b4.z, b4.w};
#pragma unroll
            for (int i = 0; i < 4; ++i)
#pragma unroll
                for (int j = 0; j < 4; ++j) acc[i][j] = fmaf(av[i], bv[j], acc[i][j]);
        }
#pragma unroll
        for (int i = 0; i < 4; ++i) {
            float bv = biasv[m + i];
            float4 r = make_float4(acc[i][0] + bv, acc[i][1] + bv,
                                   acc[i][2] + bv, acc[i][3] + bv);
            if (relu) { r.x = fmaxf(r.x, 0.f); r.y = fmaxf(r.y, 0.f);
                        r.z = fmaxf(r.z, 0.f); r.w = fmaxf(r.w, 0.f); }
            *reinterpret_cast<float4*>(&Cs[(m + i) * 36 + (tb << 2)]) = r;
        }
    }
}

// smem: hT [256][32] (reused as h2 [112][36]) + h1 [112][36] + o3 [176][36]
#define MDN_SMEM_BYTES ((256*32 + 112*36 + 176*36) * 4)

__global__ void __launch_bounds__(256, 2)
mdn_kernel(float* __restrict__ out)
{
    extern __shared__ float sm[];
    float* hT = sm;                 // [256][32], reused as h2 [112][36]
    float* h1 = hT + 256 * 32;      // [112][36]
    float* o3 = h1 + 112 * 36;      // [176][36]

    const int tid = threadIdx.x;
    const int t   = blockIdx.x >> 3;
    const int bg  = blockIdx.x & 7;

    // stage h [256][32] (already k-major in g_H)
    const float* hp = g_H + (size_t)t * 65536 + (bg << 5);
    for (int i = tid; i < 2048; i += 256) {
        int k = i >> 3, nb = i & 7;
        float4 v = *reinterpret_cast<const float4*>(hp + (size_t)k * 256 + nb * 4);
        *reinterpret_cast<float4*>(&hT[k * 32 + nb * 4]) = v;
    }
    __syncthreads();

    mdn_gemm(g_W1t, 112, 28, 256, hT, 32, h1, g_b1p, true);
    __syncthreads();
    mdn_gemm(g_W2t, 112, 28, 112, h1, 36, hT, g_b2p, true);   // h2 -> hT (reuse)
    __syncthreads();
    mdn_gemm(g_W3t, 176, 44, 112, hT, 36, o3, g_b3p, false);
    __syncthreads();

    // epilogue: softmax(first 5), exp(next 5), copy means (160)
    if (tid < 32) {
        int n = tid;
        size_t r = (size_t)((bg << 5) + n) * NSTEP + t;
        float l[5];
        float mx = -1e30f;
#pragma unroll
        for (int k = 0; k < 5; ++k) { l[k] = o3[k * 36 + n]; mx = fmaxf(mx, l[k]); }
        float s = 0.f;
#pragma unroll
        for (int k = 0; k < 5; ++k) { l[k] = __expf(l[k] - mx); s += l[k]; }
        float inv = 1.f / s;
#pragma unroll
        for (int k = 0; k < 5; ++k) out[r * 5 + k] = l[k] * inv;
#pragma unroll
        for (int k = 0; k < 5; ++k)
            out[VARBASE + r * 5 + k] = __expf(o3[(5 + k) * 36 + n]);
    }
    for (int i = tid; i < 5120; i += 256) {
        int n = i / 160, j = i - n * 160;
        size_t r = (size_t)((bg << 5) + n) * NSTEP + t;
        out[MEANBASE + r * 160 + j] = o3[(10 + j) * 36 + n];
    }
}

extern "C" void kernel_launch(void* const* d_in, const int* in_sizes, int n_in,
                              void* d_out, int out_size)
{
    const float* x    = (const float*)d_in[0];
    const float* W_ih = (const float*)d_in[1];
    const float* W_hh = (const float*)d_in[2];
    const float* b_ih = (const float*)d_in[3];
    const float* b_hh = (const float*)d_in[4];
    const float* W1   = (const float*)d_in[5];
    const float* b1   = (const float*)d_in[6];
    const float* W2   = (const float*)d_in[7];
    const float* b2   = (const float*)d_in[8];
    const float* W3   = (const float*)d_in[9];
    const float* b3   = (const float*)d_in[10];
    float* out = (float*)d_out;

    cudaFuncSetAttribute(lstm_kernel, cudaFuncAttributeMaxDynamicSharedMemorySize, LSTM_SMEM_BYTES);
    cudaFuncSetAttribute(mdn_kernel,  cudaFuncAttributeMaxDynamicSharedMemorySize, MDN_SMEM_BYTES);

    prep_kernel<<<128, 256>>>(W1, b1, W2, b2, W3, b3);
    lstm_kernel<<<128, 256, LSTM_SMEM_BYTES>>>(x, W_ih, W_hh, b_ih, b_hh);
    mdn_kernel<<<NSTEP * 8, 256, MDN_SMEM_BYTES>>>(out);
}

// round 6
// speedup vs baseline: 1.2036x; 1.1073x over previous
#include <cuda_runtime.h>
#include <cstdint>

#define TDIM   1024
#define NSTEP  1023
#define IN_DIM 35
#define KSPLIT 110

// output layout: coeff [256][1023][5] | mean [256][1023][5][32] | var [256][1023][5]
#define MEANBASE 1309440
#define VARBASE  43211520

// ---------------- device scratch (allocation-free) ----------------
__device__ float g_H[(size_t)NSTEP * 256 * 256];   // h history, [t][k=256][b=256]
__device__ float g_X[(size_t)1024 * 36 * 256];     // x transposed, [t][c=36][b=256]
__device__ float g_W1t[256 * 112];                 // k-major, M padded 100->112
__device__ float g_W2t[112 * 112];
__device__ float g_W3t[112 * 176];                 // M padded 170->176
__device__ float g_b1p[112];
__device__ float g_b2p[112];
__device__ float g_b3p[176];
__device__ unsigned g_bar[8];

// ---------------- prep 1: barriers + MDN weight transposes ----------------
__global__ void prep_w(const float* __restrict__ W1, const float* __restrict__ b1,
                       const float* __restrict__ W2, const float* __restrict__ b2,
                       const float* __restrict__ W3, const float* __restrict__ b3)
{
    int id = blockIdx.x * blockDim.x + threadIdx.x;
    int stride = gridDim.x * blockDim.x;
    if (id < 8) g_bar[id] = 0u;
    for (int i = id; i < 256 * 112; i += stride) {
        int k = i / 112, m = i - k * 112;
        g_W1t[i] = (m < 100) ? W1[m * 256 + k] : 0.f;
    }
    for (int i = id; i < 112 * 112; i += stride) {
        int k = i / 112, m = i - k * 112;
        g_W2t[i] = (k < 100 && m < 100) ? W2[m * 100 + k] : 0.f;
    }
    for (int i = id; i < 112 * 176; i += stride) {
        int k = i / 176, m = i - k * 176;
        g_W3t[i] = (k < 100 && m < 170) ? W3[m * 100 + k] : 0.f;
    }
    for (int i = id; i < 112; i += stride) {
        g_b1p[i] = (i < 100) ? b1[i] : 0.f;
        g_b2p[i] = (i < 100) ? b2[i] : 0.f;
    }
    for (int i = id; i < 176; i += stride) g_b3p[i] = (i < 170) ? b3[i] : 0.f;
}

// ---------------- prep 2: transpose x -> [t][c][b] ----------------
__global__ void prep_x(const float* __restrict__ x)
{
    int t = blockIdx.x;          // 0..1022
    int b = threadIdx.x;         // 0..255
    const float* src = x + (size_t)b * (TDIM * IN_DIM) + (size_t)t * IN_DIM;
    float* dst = g_X + (size_t)t * (36 * 256) + b;
#pragma unroll 7
    for (int c = 0; c < IN_DIM; ++c) dst[c * 256] = src[c];
    dst[35 * 256] = 0.f;   // pad row
}

__device__ __forceinline__ float sigf(float v)     { return 1.f / (1.f + __expf(-v)); }
__device__ __forceinline__ float tanhfast(float v) { return 1.f - 2.f / (__expf(2.f * v) + 1.f); }

__device__ __forceinline__ float4 ldcg4(const float* p) {
    float4 v;
    asm volatile("ld.global.cg.v4.f32 {%0,%1,%2,%3},[%4];"
                 : "=f"(v.x), "=f"(v.y), "=f"(v.z), "=f"(v.w) : "l"(p));
    return v;
}

// packed f32x2 fma: d = a*b + d (elementwise on 2 packed floats)
__device__ __forceinline__ void fma2(unsigned long long& d,
                                     unsigned long long a, unsigned long long b) {
    asm("fma.rn.f32x2 %0, %1, %2, %0;" : "+l"(d) : "l"(a), "l"(b));
}

// store float4 v as duplicated pairs: (x,x,y,y) (z,z,w,w)
__device__ __forceinline__ void dup_st(float* p, float4 v) {
    *reinterpret_cast<float4*>(p)     = make_float4(v.x, v.x, v.y, v.y);
    *reinterpret_cast<float4*>(p + 4) = make_float4(v.z, v.z, v.w, v.w);
}

// ---------------- persistent LSTM ----------------
// grid 128: jg = blockIdx>>3 (16 hid-tiles of 16), bg = blockIdx&7 (8 batch-tiles of 32)
// 256 threads; warp-group 0: x-part + h-k[0,110); group 1: h-k[110,256).
#define WHH_F  16384
#define WIH_F  2304
#define HTD_F  16384
#define XTD_F  2304
#define GST_F  2112       // [n=32][m stride 66]
#define LSTM_SMEM_BYTES ((WHH_F + WIH_F + 64 + HTD_F + XTD_F + 2*GST_F + 512) * 4)

__global__ void __launch_bounds__(256, 1)
lstm_kernel(const float* __restrict__ W_ih, const float* __restrict__ W_hh,
            const float* __restrict__ b_ih, const float* __restrict__ b_hh)
{
    extern __shared__ float sm[];
    float* Whh  = sm;                 // [k=256][m=64] k-major
    float* Wih  = Whh + WHH_F;        // [c=36][m=64]
    float* bias = Wih + WIH_F;        // [64]
    float* hTd  = bias + 64;          // [k=256][64] duplicated pairs
    float* xTd  = hTd + HTD_F;        // [c=36][64] duplicated pairs
    float* Gst0 = xTd + XTD_F;        // [n=32][m=64 pad 66]
    float* Gst1 = Gst0 + GST_F;
    float* cS   = Gst1 + GST_F;       // [16][32]

    const int tid = threadIdx.x;
    const int bg  = blockIdx.x & 7;
    const int jg  = blockIdx.x >> 3;

    // one-time weight staging (k-major transpose into smem)
    for (int i = tid; i < 64 * 64; i += 256) {
        int m  = i >> 6;
        int kc = (i & 63) << 2;
        int j  = ((m >> 4) << 8) + (jg << 4) + (m & 15);   // gate*256 + jg*16 + jh
        float4 w = *reinterpret_cast<const float4*>(&W_hh[j * 256 + kc]);
        Whh[(kc + 0) * 64 + m] = w.x;
        Whh[(kc + 1) * 64 + m] = w.y;
        Whh[(kc + 2) * 64 + m] = w.z;
        Whh[(kc + 3) * 64 + m] = w.w;
    }
    for (int i = tid; i < 36 * 64; i += 256) {
        int c = i >> 6, m = i & 63;
        int j = ((m >> 4) << 8) + (jg << 4) + (m & 15);
        Wih[c * 64 + m] = (c < 35) ? W_ih[j * 35 + c] : 0.f;
    }
    if (tid < 64) {
        int j = ((tid >> 4) << 8) + (jg << 4) + (tid & 15);
        bias[tid] = b_ih[j] + b_hh[j];
    }
    for (int i = tid; i < 512; i += 256) cS[i] = 0.f;
    // initial x(0) staging into duplicated layout
    {
        const float* xs = g_X + (bg << 5);
        for (int i = tid; i < 288; i += 256) {
            int c = i >> 3, nb = i & 7;
            float4 v = *reinterpret_cast<const float4*>(xs + c * 256 + (nb << 2));
            dup_st(&xTd[c * 64 + (nb << 3)], v);
        }
    }
    __syncthreads();

    const int wg   = tid >> 7;
    const int wtid = tid & 127;
    const int tm   = wtid & 15;       // rows 4tm..4tm+3 (2 packed pairs)
    const int tb   = wtid >> 4;       // cols 4tb..4tb+3
    float* Gs      = wg ? Gst1 : Gst0;

    const int cn  = tid & 31;         // combine: batch col
    const int cj2 = tid >> 5;         // combine: jh pair index 0..7

    for (int t = 0; t < NSTEP; ++t) {
        // stage h(t-1) into duplicated layout
        if (t > 0) {
            const float* hp = g_H + (size_t)(t - 1) * 65536 + (bg << 5);
            for (int i = tid; i < 2048; i += 256) {
                int k = i >> 3, nb = i & 7;
                float4 v = ldcg4(hp + (size_t)k * 256 + (nb << 2));
                dup_st(&hTd[k * 64 + (nb << 3)], v);
            }
        }
        // prefetch x(t+1) into registers (overlaps the GEMM below)
        float4 px0, px1;
        {
            const float* xs = g_X + (size_t)(t + 1) * (36 * 256) + (bg << 5);
            int c = tid >> 3, nb = tid & 7;
            px0 = *reinterpret_cast<const float4*>(xs + c * 256 + (nb << 2));
            if (tid < 32)
                px1 = *reinterpret_cast<const float4*>(xs + (32 + (tid >> 3)) * 256 + ((tid & 7) << 2));
        }
        __syncthreads();

        // GEMM 64x32, K split across warp-groups, FFMA2 (packed row-pairs)
        unsigned long long acc[2][4];
#pragma unroll
        for (int p = 0; p < 2; ++p)
#pragma unroll
            for (int j = 0; j < 4; ++j) acc[p][j] = 0ull;

        const int aoff = tm << 2;
        const int boff = tb << 3;
        if (wg == 0) {
#pragma unroll 4
            for (int c = 0; c < 36; ++c) {
                ulonglong2 a   = *reinterpret_cast<const ulonglong2*>(&Wih[c * 64 + aoff]);
                ulonglong2 r01 = *reinterpret_cast<const ulonglong2*>(&xTd[c * 64 + boff]);
                fma2(acc[0][0], a.x, r01.x); fma2(acc[1][0], a.y, r01.x);
                fma2(acc[0][1], a.x, r01.y); fma2(acc[1][1], a.y, r01.y);
                ulonglong2 r23 = *reinterpret_cast<const ulonglong2*>(&xTd[c * 64 + boff + 4]);
                fma2(acc[0][2], a.x, r23.x); fma2(acc[1][2], a.y, r23.x);
                fma2(acc[0][3], a.x, r23.y); fma2(acc[1][3], a.y, r23.y);
            }
            if (t > 0) {
#pragma unroll 5
                for (int k = 0; k < KSPLIT; ++k) {
                    ulonglong2 a   = *reinterpret_cast<const ulonglong2*>(&Whh[k * 64 + aoff]);
                    ulonglong2 r01 = *reinterpret_cast<const ulonglong2*>(&hTd[k * 64 + boff]);
                    fma2(acc[0][0], a.x, r01.x); fma2(acc[1][0], a.y, r01.x);
                    fma2(acc[0][1], a.x, r01.y); fma2(acc[1][1], a.y, r01.y);
                    ulonglong2 r23 = *reinterpret_cast<const ulonglong2*>(&hTd[k * 64 + boff + 4]);
                    fma2(acc[0][2], a.x, r23.x); fma2(acc[1][2], a.y, r23.x);
                    fma2(acc[0][3], a.x, r23.y); fma2(acc[1][3], a.y, r23.y);
                }
            }
        } else if (t > 0) {
#pragma unroll 2
            for (int k = KSPLIT; k < 256; ++k) {
                ulonglong2 a   = *reinterpret_cast<const ulonglong2*>(&Whh[k * 64 + aoff]);
                ulonglong2 r01 = *reinterpret_cast<const ulonglong2*>(&hTd[k * 64 + boff]);
                fma2(acc[0][0], a.x, r01.x); fma2(acc[1][0], a.y, r01.x);
                fma2(acc[0][1], a.x, r01.y); fma2(acc[1][1], a.y, r01.y);
                ulonglong2 r23 = *reinterpret_cast<const ulonglong2*>(&hTd[k * 64 + boff + 4]);
                fma2(acc[0][2], a.x, r23.x); fma2(acc[1][2], a.y, r23.x);
                fma2(acc[0][3], a.x, r23.y); fma2(acc[1][3], a.y, r23.y);
            }
        }
        // store packed gates transposed: Gs[n][m], u64 covers rows (m, m+1)
#pragma unroll
        for (int j = 0; j < 4; ++j) {
#pragma unroll
            for (int p = 0; p < 2; ++p)
                *reinterpret_cast<unsigned long long*>(
                    &Gs[((tb << 2) + j) * 66 + (tm << 2) + (p << 1)]) = acc[p][j];
        }
        __syncthreads();

        // gate combine: 2 cells/thread (jh = 2*cj2, 2*cj2+1), col cn
        {
            int base = cn * 66 + (cj2 << 1);
            float2 aI = *reinterpret_cast<const float2*>(&Gst0[base]);
            float2 bI = *reinterpret_cast<const float2*>(&Gst1[base]);
            float2 aF = *reinterpret_cast<const float2*>(&Gst0[base + 16]);
            float2 bF = *reinterpret_cast<const float2*>(&Gst1[base + 16]);
            float2 aG = *reinterpret_cast<const float2*>(&Gst0[base + 32]);
            float2 bG = *reinterpret_cast<const float2*>(&Gst1[base + 32]);
            float2 aO = *reinterpret_cast<const float2*>(&Gst0[base + 48]);
            float2 bO = *reinterpret_cast<const float2*>(&Gst1[base + 48]);
            float2 sI = *reinterpret_cast<const float2*>(&bias[(cj2 << 1)]);
            float2 sF = *reinterpret_cast<const float2*>(&bias[16 + (cj2 << 1)]);
            float2 sG = *reinterpret_cast<const float2*>(&bias[32 + (cj2 << 1)]);
            float2 sO = *reinterpret_cast<const float2*>(&bias[48 + (cj2 << 1)]);
            float* hrow = g_H + (size_t)t * 65536 + (size_t)((jg << 4) + (cj2 << 1)) * 256
                          + (bg << 5) + cn;
#define CELL(L, off)                                                              \
            {                                                                     \
                float iv = sigf(aI.L + bI.L + sI.L);                              \
                float fv = sigf(aF.L + bF.L + sF.L);                              \
                float gv = tanhfast(aG.L + bG.L + sG.L);                          \
                float ov = sigf(aO.L + bO.L + sO.L);                              \
                int ci = ((cj2 << 1) + off) * 32 + cn;                            \
                float cv = fv * cS[ci] + iv * gv;                                 \
                cS[ci] = cv;                                                      \
                hrow[off * 256] = ov * tanhfast(cv);                              \
            }
            CELL(x, 0) CELL(y, 1)
#undef CELL
        }
        // write prefetched x(t+1) into xTd (consumed next iter after barrier sync)
        {
            int c = tid >> 3, nb = tid & 7;
            dup_st(&xTd[c * 64 + (nb << 3)], px0);
            if (tid < 32)
                dup_st(&xTd[(32 + (tid >> 3)) * 64 + ((tid & 7) << 3)], px1);
        }
        __syncthreads();

        // inter-block barrier (16 jg-blocks sharing this bg)
        if (tid == 0) {
            __threadfence();
            asm volatile("red.release.gpu.global.add.u32 [%0],%1;"
                         :: "l"(&g_bar[bg]), "r"(1u) : "memory");
            unsigned target = (unsigned)(t + 1) << 4;
            unsigned v;
            do {
                asm volatile("ld.acquire.gpu.global.u32 %0,[%1];"
                             : "=r"(v) : "l"(&g_bar[bg]));
            } while (v < target);
        }
        __syncthreads();
    }
}

// ---------------- MDN head ----------------
__device__ __forceinline__ void mdn_gemm(
    const float* __restrict__ At, int ldA, int mTiles, int K,
    const float* __restrict__ Bs, int ldb, float* __restrict__ Cs,
    const float* __restrict__ biasv, bool relu)
{
    for (int tile = threadIdx.x; tile < mTiles * 8; tile += blockDim.x) {
        int tm = tile % mTiles, tb = tile / mTiles;
        int m = tm << 2;
        const float* Ap = At + m;
        const float* Bp = Bs + (tb << 2);
        float acc[4][4];
#pragma unroll
        for (int i = 0; i < 4; ++i)
#pragma unroll
            for (int j = 0; j < 4; ++j) acc[i][j] = 0.f;
#pragma unroll 4
        for (int k = 0; k < K; ++k) {
            float4 a  = *reinterpret_cast<const float4*>(Ap + k * ldA);
            float4 b4 = *reinterpret_cast<const float4*>(Bp + k * ldb);
            float av[4] = {a.x, a.y, a.z, a.w};
            float bv[4] = {b4.x, b4.y, b4.z, b4.w};
#pragma unroll
            for (int i = 0; i < 4; ++i)
#pragma unroll
                for (int j = 0; j < 4; ++j) acc[i][j] = fmaf(av[i], bv[j], acc[i][j]);
        }
#pragma unroll
        for (int i = 0; i < 4; ++i) {
            float bv = biasv[m + i];
            float4 r = make_float4(acc[i][0] + bv, acc[i][1] + bv,
                                   acc[i][2] + bv, acc[i][3] + bv);
            if (relu) { r.x = fmaxf(r.x, 0.f); r.y = fmaxf(r.y, 0.f);
                        r.z = fmaxf(r.z, 0.f); r.w = fmaxf(r.w, 0.f); }
            *reinterpret_cast<float4*>(&Cs[(m + i) * 36 + (tb << 2)]) = r;
        }
    }
}

#define MDN_SMEM_BYTES ((256*32 + 112*36 + 176*36) * 4)

__global__ void __launch_bounds__(256, 2)
mdn_kernel(float* __restrict__ out)
{
    extern __shared__ float sm[];
    float* hT = sm;                 // [256][32], reused as h2 [112][36]
    float* h1 = hT + 256 * 32;      // [112][36]
    float* o3 = h1 + 112 * 36;      // [176][36]

    const int tid = threadIdx.x;
    const int t   = blockIdx.x >> 3;
    const int bg  = blockIdx.x & 7;

    const float* hp = g_H + (size_t)t * 65536 + (bg << 5);
    for (int i = tid; i < 2048; i += 256) {
        int k = i >> 3, nb = i & 7;
        float4 v = *reinterpret_cast<const float4*>(hp + (size_t)k * 256 + (nb << 2));
        *reinterpret_cast<float4*>(&hT[k * 32 + (nb << 2)]) = v;
    }
    __syncthreads();

    mdn_gemm(g_W1t, 112, 28, 256, hT, 32, h1, g_b1p, true);
    __syncthreads();
    mdn_gemm(g_W2t, 112, 28, 112, h1, 36, hT, g_b2p, true);   // h2 -> hT (reuse)
    __syncthreads();
    mdn_gemm(g_W3t, 176, 44, 112, hT, 36, o3, g_b3p, false);
    __syncthreads();

    if (tid < 32) {
        int n = tid;
        size_t r = (size_t)((bg << 5) + n) * NSTEP + t;
        float l[5];
        float mx = -1e30f;
#pragma unroll
        for (int k = 0; k < 5; ++k) { l[k] = o3[k * 36 + n]; mx = fmaxf(mx, l[k]); }
        float s = 0.f;
#pragma unroll
        for (int k = 0; k < 5; ++k) { l[k] = __expf(l[k] - mx); s += l[k]; }
        float inv = 1.f / s;
#pragma unroll
        for (int k = 0; k < 5; ++k) out[r * 5 + k] = l[k] * inv;
#pragma unroll
        for (int k = 0; k < 5; ++k)
            out[VARBASE + r * 5 + k] = __expf(o3[(5 + k) * 36 + n]);
    }
    for (int i = tid; i < 5120; i += 256) {
        int n = i / 160, j = i - n * 160;
        size_t r = (size_t)((bg << 5) + n) * NSTEP + t;
        out[MEANBASE + r * 160 + j] = o3[(10 + j) * 36 + n];
    }
}

extern "C" void kernel_launch(void* const* d_in, const int* in_sizes, int n_in,
                              void* d_out, int out_size)
{
    const float* x    = (const float*)d_in[0];
    const float* W_ih = (const float*)d_in[1];
    const float* W_hh = (const float*)d_in[2];
    const float* b_ih = (const float*)d_in[3];
    const float* b_hh = (const float*)d_in[4];
    const float* W1   = (const float*)d_in[5];
    const float* b1   = (const float*)d_in[6];
    const float* W2   = (const float*)d_in[7];
    const float* b2   = (const float*)d_in[8];
    const float* W3   = (const float*)d_in[9];
    const float* b3   = (const float*)d_in[10];
    float* out = (float*)d_out;

    cudaFuncSetAttribute(lstm_kernel, cudaFuncAttributeMaxDynamicSharedMemorySize, LSTM_SMEM_BYTES);
    cudaFuncSetAttribute(mdn_kernel,  cudaFuncAttributeMaxDynamicSharedMemorySize, MDN_SMEM_BYTES);

    prep_w<<<128, 256>>>(W1, b1, W2, b2, W3, b3);
    prep_x<<<NSTEP, 256>>>(x);
    lstm_kernel<<<128, 256, LSTM_SMEM_BYTES>>>(W_ih, W_hh, b_ih, b_hh);
    mdn_kernel<<<NSTEP * 8, 256, MDN_SMEM_BYTES>>>(out);
}

// round 7
// speedup vs baseline: 1.2132x; 1.0080x over previous
#include <cuda_runtime.h>
#include <cstdint>

#define TDIM   1024
#define NSTEP  1023
#define IN_DIM 35

// output layout: coeff [256][1023][5] | mean [256][1023][5][32] | var [256][1023][5]
#define MEANBASE 1309440
#define VARBASE  43211520

// ---------------- device scratch (allocation-free) ----------------
__device__ float g_H[(size_t)NSTEP * 256 * 256];    // h history, [t][k=256][b=256]
__device__ float g_GX[(size_t)NSTEP * 1024 * 256];  // x-projection, [t][j=1024][b=256]
__device__ float g_W1t[256 * 112];                  // k-major, M padded 100->112
__device__ float g_W2t[112 * 112];
__device__ float g_W3t[112 * 176];                  // M padded 170->176
__device__ float g_b1p[112];
__device__ float g_b2p[112];
__device__ float g_b3p[176];
__device__ unsigned g_bar[8];

// ---------------- prep: barriers + MDN weight transposes ----------------
__global__ void prep_w(const float* __restrict__ W1, const float* __restrict__ b1,
                       const float* __restrict__ W2, const float* __restrict__ b2,
                       const float* __restrict__ W3, const float* __restrict__ b3)
{
    int id = blockIdx.x * blockDim.x + threadIdx.x;
    int stride = gridDim.x * blockDim.x;
    if (id < 8) g_bar[id] = 0u;
    for (int i = id; i < 256 * 112; i += stride) {
        int k = i / 112, m = i - k * 112;
        g_W1t[i] = (m < 100) ? W1[m * 256 + k] : 0.f;
    }
    for (int i = id; i < 112 * 112; i += stride) {
        int k = i / 112, m = i - k * 112;
        g_W2t[i] = (k < 100 && m < 100) ? W2[m * 100 + k] : 0.f;
    }
    for (int i = id; i < 112 * 176; i += stride) {
        int k = i / 176, m = i - k * 176;
        g_W3t[i] = (k < 100 && m < 170) ? W3[m * 100 + k] : 0.f;
    }
    for (int i = id; i < 112; i += stride) {
        g_b1p[i] = (i < 100) ? b1[i] : 0.f;
        g_b2p[i] = (i < 100) ? b2[i] : 0.f;
    }
    for (int i = id; i < 176; i += stride) g_b3p[i] = (i < 170) ? b3[i] : 0.f;
}

// ---------------- x-projection: GX[t][j][b] = sum_c W_ih[j][c] * x[b][t][c] ----------------
// grid (1023, 16, 4): t, jtile(64 rows), btile(64 cols); 256 threads, thread = 4j x 4b
__global__ void __launch_bounds__(256)
xproj_kernel(const float* __restrict__ x, const float* __restrict__ W_ih)
{
    __shared__ float Ws[IN_DIM][64];
    __shared__ float xs[IN_DIM][64];
    const int tid = threadIdx.x;
    const int t  = blockIdx.x;
    const int jt = blockIdx.y;
    const int bt = blockIdx.z;

    for (int i = tid; i < 64 * IN_DIM; i += 256) {
        int m = i / IN_DIM, c = i - m * IN_DIM;
        Ws[c][m] = W_ih[(jt * 64 + m) * IN_DIM + c];
    }
    for (int i = tid; i < 64 * IN_DIM; i += 256) {
        int n = i / IN_DIM, c = i - n * IN_DIM;
        xs[c][n] = x[((size_t)(bt * 64 + n) * TDIM + t) * IN_DIM + c];
    }
    __syncthreads();

    const int tm = tid >> 4;   // j quad (coalesced stores: tb fast)
    const int tb = tid & 15;   // b quad
    float acc[4][4];
#pragma unroll
    for (int i = 0; i < 4; ++i)
#pragma unroll
        for (int j = 0; j < 4; ++j) acc[i][j] = 0.f;
#pragma unroll 5
    for (int c = 0; c < IN_DIM; ++c) {
        float4 a  = *reinterpret_cast<const float4*>(&Ws[c][tm << 2]);
        float4 b4 = *reinterpret_cast<const float4*>(&xs[c][tb << 2]);
        float av[4] = {a.x, a.y, a.z, a.w};
        float bv[4] = {b4.x, b4.y, b4.z, b4.w};
#pragma unroll
        for (int i = 0; i < 4; ++i)
#pragma unroll
            for (int j = 0; j < 4; ++j) acc[i][j] = fmaf(av[i], bv[j], acc[i][j]);
    }
    float* dst = g_GX + (size_t)t * 262144 + (size_t)(jt * 64 + (tm << 2)) * 256
                 + bt * 64 + (tb << 2);
#pragma unroll
    for (int i = 0; i < 4; ++i)
        *reinterpret_cast<float4*>(dst + (size_t)i * 256) =
            make_float4(acc[i][0], acc[i][1], acc[i][2], acc[i][3]);
}

__device__ __forceinline__ float sigf(float v)     { return 1.f / (1.f + __expf(-v)); }
__device__ __forceinline__ float tanhfast(float v) { return 1.f - 2.f / (__expf(2.f * v) + 1.f); }

__device__ __forceinline__ float4 ldcg4(const float* p) {
    float4 v;
    asm volatile("ld.global.cg.v4.f32 {%0,%1,%2,%3},[%4];"
                 : "=f"(v.x), "=f"(v.y), "=f"(v.z), "=f"(v.w) : "l"(p));
    return v;
}
__device__ __forceinline__ void fma2(unsigned long long& d,
                                     unsigned long long a, unsigned long long b) {
    asm("fma.rn.f32x2 %0, %1, %2, %0;" : "+l"(d) : "l"(a), "l"(b));
}
__device__ __forceinline__ void dup_st(float* p, float4 v) {
    *reinterpret_cast<float4*>(p)     = make_float4(v.x, v.x, v.y, v.y);
    *reinterpret_cast<float4*>(p + 4) = make_float4(v.z, v.z, v.w, v.w);
}

// ---------------- persistent LSTM ----------------
// grid 128: jg = blockIdx>>3 (16 hid-tiles of 16), bg = blockIdx&7 (8 batch-tiles of 32)
// 512 threads = 4 warps/SMSP; 4-way K split over k=[wg*64, wg*64+64).
#define WHH_F  16384
#define HTD_F  16384
#define GST_F  2112       // [n=32][m stride 66]
#define LSTM_SMEM_BYTES ((WHH_F + 64 + HTD_F + 4*GST_F + 512) * 4)

__global__ void __launch_bounds__(512, 1)
lstm_kernel(const float* __restrict__ W_hh,
            const float* __restrict__ b_ih, const float* __restrict__ b_hh)
{
    extern __shared__ float sm[];
    float* Whh  = sm;                 // [k=256][m=64] k-major
    float* bias = Whh + WHH_F;        // [64]
    float* hTd  = bias + 64;          // [k=256][64] duplicated pairs
    float* Gst  = hTd + HTD_F;        // 4 x [n=32][m=64 pad 66]
    float* cS   = Gst + 4 * GST_F;    // [16][32]

    const int tid = threadIdx.x;
    const int bg  = blockIdx.x & 7;
    const int jg  = blockIdx.x >> 3;

    // one-time weight staging (k-major transpose into smem)
    for (int i = tid; i < 64 * 64; i += 512) {
        int m  = i >> 6;
        int kc = (i & 63) << 2;
        int j  = ((m >> 4) << 8) + (jg << 4) + (m & 15);   // gate*256 + jg*16 + jh
        float4 w = *reinterpret_cast<const float4*>(&W_hh[j * 256 + kc]);
        Whh[(kc + 0) * 64 + m] = w.x;
        Whh[(kc + 1) * 64 + m] = w.y;
        Whh[(kc + 2) * 64 + m] = w.z;
        Whh[(kc + 3) * 64 + m] = w.w;
    }
    if (tid < 64) {
        int j = ((tid >> 4) << 8) + (jg << 4) + (tid & 15);
        bias[tid] = b_ih[j] + b_hh[j];
    }
    if (tid < 512) cS[tid] = 0.f;
    __syncthreads();

    const int wg   = tid >> 7;        // K-split group 0..3
    const int wtid = tid & 127;
    const int tm   = wtid & 15;       // rows 4tm..4tm+3 (2 packed pairs)
    const int tb   = wtid >> 4;       // cols 4tb..4tb+3
    float* Gs      = Gst + wg * GST_F;

    const int cjh = tid >> 5;         // combine: jh 0..15
    const int cn  = tid & 31;         // combine: batch col
    const size_t gxoff = (size_t)((jg << 4) + cjh) * 256 + (bg << 5) + cn;

    for (int t = 0; t < NSTEP; ++t) {
        // early-issued gx loads (constant buffer, latency hidden by GEMM)
        const float* gp = g_GX + (size_t)t * 262144 + gxoff;
        float gxi = gp[0];
        float gxf = gp[65536];
        float gxg = gp[131072];
        float gxo = gp[196608];

        // stage h(t-1) into duplicated layout
        if (t > 0) {
            const float* hp = g_H + (size_t)(t - 1) * 65536 + (bg << 5);
#pragma unroll
            for (int s = 0; s < 4; ++s) {
                int i = tid + s * 512;
                int k = i >> 3, nb = i & 7;
                float4 v = ldcg4(hp + (size_t)k * 256 + (nb << 2));
                dup_st(&hTd[k * 64 + (nb << 3)], v);
            }
        }
        __syncthreads();

        // GEMM 64x32, K=256 split 4 ways, FFMA2 packed row-pairs
        unsigned long long acc[2][4];
#pragma unroll
        for (int p = 0; p < 2; ++p)
#pragma unroll
            for (int j = 0; j < 4; ++j) acc[p][j] = 0ull;

        if (t > 0) {
            const int aoff = tm << 2;
            const int boff = tb << 3;
            const int k0 = wg << 6;
#pragma unroll 8
            for (int k = k0; k < k0 + 64; ++k) {
                ulonglong2 a   = *reinterpret_cast<const ulonglong2*>(&Whh[k * 64 + aoff]);
                ulonglong2 r01 = *reinterpret_cast<const ulonglong2*>(&hTd[k * 64 + boff]);
                fma2(acc[0][0], a.x, r01.x); fma2(acc[1][0], a.y, r01.x);
                fma2(acc[0][1], a.x, r01.y); fma2(acc[1][1], a.y, r01.y);
                ulonglong2 r23 = *reinterpret_cast<const ulonglong2*>(&hTd[k * 64 + boff + 4]);
                fma2(acc[0][2], a.x, r23.x); fma2(acc[1][2], a.y, r23.x);
                fma2(acc[0][3], a.x, r23.y); fma2(acc[1][3], a.y, r23.y);
            }
        }
        // store packed gates transposed: Gs[n][m], u64 covers rows (m, m+1)
#pragma unroll
        for (int j = 0; j < 4; ++j)
#pragma unroll
            for (int p = 0; p < 2; ++p)
                *reinterpret_cast<unsigned long long*>(
                    &Gs[((tb << 2) + j) * 66 + (tm << 2) + (p << 1)]) = acc[p][j];
        __syncthreads();

        // combine: 1 cell/thread; sum 4 K-partials + gx + bias
        {
            int base = cn * 66 + cjh;
            float vi = gxi + bias[cjh];
            float vf = gxf + bias[16 + cjh];
            float vg = gxg + bias[32 + cjh];
            float vo = gxo + bias[48 + cjh];
#pragma unroll
            for (int p = 0; p < 4; ++p) {
                const float* G = Gst + p * GST_F + base;
                vi += G[0]; vf += G[16]; vg += G[32]; vo += G[48];
            }
            float iv = sigf(vi), fv = sigf(vf), gv = tanhfast(vg), ov = sigf(vo);
            int ci = cjh * 32 + cn;
            float cv = fv * cS[ci] + iv * gv;
            cS[ci] = cv;
            g_H[(size_t)t * 65536 + (size_t)((jg << 4) + cjh) * 256 + (bg << 5) + cn]
                = ov * tanhfast(cv);
        }
        __syncthreads();

        // inter-block barrier (16 jg-blocks sharing this bg)
        if (tid == 0) {
            __threadfence();
            asm volatile("red.release.gpu.global.add.u32 [%0],%1;"
                         :: "l"(&g_bar[bg]), "r"(1u) : "memory");
            unsigned target = (unsigned)(t + 1) << 4;
            unsigned v;
            do {
                asm volatile("ld.acquire.gpu.global.u32 %0,[%1];"
                             : "=r"(v) : "l"(&g_bar[bg]));
            } while (v < target);
        }
        __syncthreads();
    }
}

// ---------------- MDN head ----------------
__device__ __forceinline__ void mdn_gemm(
    const float* __restrict__ At, int ldA, int mTiles, int K,
    const float* __restrict__ Bs, int ldb, float* __restrict__ Cs,
    const float* __restrict__ biasv, bool relu)
{
    for (int tile = threadIdx.x; tile < mTiles * 8; tile += blockDim.x) {
        int tm = tile % mTiles, tb = tile / mTiles;
        int m = tm << 2;
        const float* Ap = At + m;
        const float* Bp = Bs + (tb << 2);
        float acc[4][4];
#pragma unroll
        for (int i = 0; i < 4; ++i)
#pragma unroll
            for (int j = 0; j < 4; ++j) acc[i][j] = 0.f;
#pragma unroll 4
        for (int k = 0; k < K; ++k) {
            float4 a  = *reinterpret_cast<const float4*>(Ap + k * ldA);
            float4 b4 = *reinterpret_cast<const float4*>(Bp + k * ldb);
            float av[4] = {a.x, a.y, a.z, a.w};
            float bv[4] = {b4.x, b4.y, b4.z, b4.w};
#pragma unroll
            for (int i = 0; i < 4; ++i)
#pragma unroll
                for (int j = 0; j < 4; ++j) acc[i][j] = fmaf(av[i], bv[j], acc[i][j]);
        }
#pragma unroll
        for (int i = 0; i < 4; ++i) {
            float bv = biasv[m + i];
            float4 r = make_float4(acc[i][0] + bv, acc[i][1] + bv,
                                   acc[i][2] + bv, acc[i][3] + bv);
            if (relu) { r.x = fmaxf(r.x, 0.f); r.y = fmaxf(r.y, 0.f);
                        r.z = fmaxf(r.z, 0.f); r.w = fmaxf(r.w, 0.f); }
            *reinterpret_cast<float4*>(&Cs[(m + i) * 36 + (tb << 2)]) = r;
        }
    }
}

#define MDN_SMEM_BYTES ((256*32 + 112*36 + 176*36) * 4)

__global__ void __launch_bounds__(256, 2)
mdn_kernel(float* __restrict__ out)
{
    extern __shared__ float sm[];
    float* hT = sm;                 // [256][32], reused as h2 [112][36]
    float* h1 = hT + 256 * 32;      // [112][36]
    float* o3 = h1 + 112 * 36;      // [176][36]

    const int tid = threadIdx.x;
    const int t   = blockIdx.x >> 3;
    const int bg  = blockIdx.x & 7;

    const float* hp = g_H + (size_t)t * 65536 + (bg << 5);
    for (int i = tid; i < 2048; i += 256) {
        int k = i >> 3, nb = i & 7;
        float4 v = *reinterpret_cast<const float4*>(hp + (size_t)k * 256 + (nb << 2));
        *reinterpret_cast<float4*>(&hT[k * 32 + (nb << 2)]) = v;
    }
    __syncthreads();

    mdn_gemm(g_W1t, 112, 28, 256, hT, 32, h1, g_b1p, true);
    __syncthreads();
    mdn_gemm(g_W2t, 112, 28, 112, h1, 36, hT, g_b2p, true);   // h2 -> hT (reuse)
    __syncthreads();
    mdn_gemm(g_W3t, 176, 44, 112, hT, 36, o3, g_b3p, false);
    __syncthreads();

    if (tid < 32) {
        int n = tid;
        size_t r = (size_t)((bg << 5) + n) * NSTEP + t;
        float l[5];
        float mx = -1e30f;
#pragma unroll
        for (int k = 0; k < 5; ++k) { l[k] = o3[k * 36 + n]; mx = fmaxf(mx, l[k]); }
        float s = 0.f;
#pragma unroll
        for (int k = 0; k < 5; ++k) { l[k] = __expf(l[k] - mx); s += l[k]; }
        float inv = 1.f / s;
#pragma unroll
        for (int k = 0; k < 5; ++k) out[r * 5 + k] = l[k] * inv;
#pragma unroll
        for (int k = 0; k < 5; ++k)
            out[VARBASE + r * 5 + k] = __expf(o3[(5 + k) * 36 + n]);
    }
    for (int i = tid; i < 5120; i += 256) {
        int n = i / 160, j = i - n * 160;
        size_t r = (size_t)((bg << 5) + n) * NSTEP + t;
        out[MEANBASE + r * 160 + j] = o3[(10 + j) * 36 + n];
    }
}

extern "C" void kernel_launch(void* const* d_in, const int* in_sizes, int n_in,
                              void* d_out, int out_size)
{
    const float* x    = (const float*)d_in[0];
    const float* W_ih = (const float*)d_in[1];
    const float* W_hh = (const float*)d_in[2];
    const float* b_ih = (const float*)d_in[3];
    const float* b_hh = (const float*)d_in[4];
    const float* W1   = (const float*)d_in[5];
    const float* b1   = (const float*)d_in[6];
    const float* W2   = (const float*)d_in[7];
    const float* b2   = (const float*)d_in[8];
    const float* W3   = (const float*)d_in[9];
    const float* b3   = (const float*)d_in[10];
    float* out = (float*)d_out;

    cudaFuncSetAttribute(lstm_kernel, cudaFuncAttributeMaxDynamicSharedMemorySize, LSTM_SMEM_BYTES);
    cudaFuncSetAttribute(mdn_kernel,  cudaFuncAttributeMaxDynamicSharedMemorySize, MDN_SMEM_BYTES);

    prep_w<<<128, 256>>>(W1, b1, W2, b2, W3, b3);
    xproj_kernel<<<dim3(NSTEP, 16, 4), 256>>>(x, W_ih);
    lstm_kernel<<<128, 512, LSTM_SMEM_BYTES>>>(W_hh, b_ih, b_hh);
    mdn_kernel<<<NSTEP * 8, 256, MDN_SMEM_BYTES>>>(out);
}